// round 13
// baseline (speedup 1.0000x reference)
#include <cuda_runtime.h>
#include <cuda_fp16.h>

#define NN 50000
#define TOPK 32
#define INC 128
#define OUTC 64
#define BN_EPS 1e-5f

// scratch (static __device__: allocation-free per harness rules)
__device__ __half2 g_xlin_h[NN * 32];   // x_lin in fp16: halves k2 gather traffic
__device__ float g_ai[NN];
__device__ float g_aj[NN];
__device__ float g_bnsum[OUTC];
__device__ float g_bnsq[OUTC];
__device__ int   g_idx64;
__device__ float g_wt[INC * OUTC];      // W^T: [k][c] row-major, ld = 64

// packed f32x2 ops (Blackwell sm_10x; FFMA2 only reachable via PTX)
#define FMA_F32X2(acc, a, b) \
    asm("fma.rn.f32x2 %0, %1, %2, %0;" : "+l"(acc) : "l"(a), "l"(b))
#define DUP_F32X2(out, v) \
    asm("mov.b64 %0, {%1, %1};" : "=l"(out) : "r"(__float_as_uint(v)))
#define UNPACK_F32X2(lo, hi, in) \
    asm("mov.b64 {%0, %1}, %2;" : "=r"(lo), "=r"(hi) : "l"(in))

// ---------------------------------------------------------------------------
// Prep: transpose W to [k][c], zero BN accumulators, detect index width.
// ---------------------------------------------------------------------------
__global__ void k0_prep(const float* __restrict__ lin_w, const void* __restrict__ eidx)
{
    const int tid = threadIdx.x;
    for (int i = tid; i < INC * OUTC; i += 256) {
        int c = i >> 7, k = i & 127;          // lin_w is [64][128] row-major
        g_wt[k * OUTC + c] = lin_w[i];
    }
    if (tid < OUTC) { g_bnsum[tid] = 0.f; g_bnsq[tid] = 0.f; }
    if (tid == 0) {
        // int64 data has zero high words (all indices < 50000);
        // int32 data has words[1,3,5,7] = src[1,3,5,7] >= 1 always.
        const unsigned* w = (const unsigned*)eidx;
        g_idx64 = ((w[1] | w[3] | w[5] | w[7]) == 0u) ? 1 : 0;
    }
}

// ---------------------------------------------------------------------------
// Kernel 1: x_lin = x @ W^T, SIMT register-tiled with packed f32x2 FMAs.
// Block = 256 thr computes 128 nodes x 64 ch (W staged ONCE per 128 nodes,
// same traffic as the 73.3us version); thread = 4 nodes x 8 channels
// (4 channel PAIRS at c = cg*2 + 16j -> conflict-free b64 W loads).
// 256 thr @ ~75 regs -> ~3 blocks (24 warps)/SM vs 10 warps before:
// LDS latency and DUP->FFMA2 dependency chains get covered.
// Epilogue: fp16 xlin write + per-node attention scalars a_i / a_j (fp32).
// ---------------------------------------------------------------------------
__global__ __launch_bounds__(256) void k1_gemm(
    const float* __restrict__ x, const float* __restrict__ emb,
    const float* __restrict__ att_i, const float* __restrict__ att_j,
    const float* __restrict__ att_em_i, const float* __restrict__ att_em_j)
{
    __shared__ float s_w[INC * OUTC];     // 32 KB, [k][64]
    __shared__ float s_x[16 * 128];       // 8 KB,  [kk][node]
    __shared__ float s_att[4][OUTC];

    const int tid = threadIdx.x;

    {   // stage W (coalesced float4, all 256 threads)
        const float4* src = (const float4*)g_wt;
        float4*       dst = (float4*)s_w;
        #pragma unroll
        for (int i = 0; i < 8; ++i) dst[tid + i * 256] = src[tid + i * 256];
    }
    if (tid < OUTC) {
        s_att[0][tid] = att_i[tid];
        s_att[1][tid] = att_j[tid];
        s_att[2][tid] = att_em_i[tid];
        s_att[3][tid] = att_em_j[tid];
    }

    int nbase = blockIdx.x * 128;
    if (nbase + 128 > NN) nbase = NN - 128;   // overlap rows: identical rewrite, benign

    const int ng  = tid >> 3;                 // 32 node-groups of 4
    const int cg  = tid & 7;                  // 8 channel-groups
    const int nd0 = ng << 2;

    unsigned long long acc[4][4];
    #pragma unroll
    for (int n = 0; n < 4; ++n)
        #pragma unroll
        for (int j = 0; j < 4; ++j) acc[n][j] = 0ULL;   // packed {+0,+0}

    // x prefetch: thread owns node (tid&127), k-half (tid>>7): 8 k's per chunk
    const int xnode = tid & 127, xhalf = tid >> 7;
    const float4* xrow = (const float4*)(x + (size_t)(nbase + xnode) * INC);
    float4 v0 = xrow[xhalf * 2 + 0];
    float4 v1 = xrow[xhalf * 2 + 1];

    #pragma unroll 1
    for (int kc = 0; kc < 8; ++kc) {
        __syncthreads();
        {
            float* sx = &s_x[xhalf * 8 * 128 + xnode];
            sx[0 * 128] = v0.x; sx[1 * 128] = v0.y;
            sx[2 * 128] = v0.z; sx[3 * 128] = v0.w;
            sx[4 * 128] = v1.x; sx[5 * 128] = v1.y;
            sx[6 * 128] = v1.z; sx[7 * 128] = v1.w;
        }
        __syncthreads();

        if (kc < 7) {                          // prefetch next chunk (overlaps compute)
            v0 = xrow[(kc + 1) * 4 + xhalf * 2 + 0];
            v1 = xrow[(kc + 1) * 4 + xhalf * 2 + 1];
        }

        #pragma unroll
        for (int kk = 0; kk < 16; ++kk) {
            float4 xa = *(const float4*)&s_x[kk * 128 + nd0];
            unsigned long long xd[4];
            DUP_F32X2(xd[0], xa.x); DUP_F32X2(xd[1], xa.y);
            DUP_F32X2(xd[2], xa.z); DUP_F32X2(xd[3], xa.w);

            const unsigned long long* wp =
                (const unsigned long long*)&s_w[(kc * 16 + kk) * OUTC];
            unsigned long long w0 = wp[cg];
            unsigned long long w1 = wp[cg + 8];
            unsigned long long w2 = wp[cg + 16];
            unsigned long long w3 = wp[cg + 24];

            #pragma unroll
            for (int n = 0; n < 4; ++n) {
                FMA_F32X2(acc[n][0], xd[n], w0);
                FMA_F32X2(acc[n][1], xd[n], w1);
                FMA_F32X2(acc[n][2], xd[n], w2);
                FMA_F32X2(acc[n][3], xd[n], w3);
            }
        }
    }

    // epilogue: fp16 xlin write + attention scalars (8-lane shuffle reduce)
    #pragma unroll
    for (int n = 0; n < 4; ++n) {
        const int node = nbase + nd0 + n;
        __half2*      xlo  = g_xlin_h + (size_t)node * 32;
        const float2* erow = (const float2*)emb + (size_t)node * 32;
        float ai = 0.f, aj = 0.f;
        #pragma unroll
        for (int j = 0; j < 4; ++j) {
            unsigned lo_u, hi_u;
            UNPACK_F32X2(lo_u, hi_u, acc[n][j]);
            float lo = __uint_as_float(lo_u), hi = __uint_as_float(hi_u);
            const int c = cg * 2 + 16 * j;
            xlo[cg + 8 * j] = __floats2half2_rn(lo, hi);
            float2 e = erow[cg + 8 * j];
            ai += lo * s_att[0][c] + hi * s_att[0][c + 1]
                + e.x * s_att[2][c] + e.y * s_att[2][c + 1];
            aj += lo * s_att[1][c] + hi * s_att[1][c + 1]
                + e.x * s_att[3][c] + e.y * s_att[3][c + 1];
        }
        ai += __shfl_xor_sync(0xffffffffu, ai, 1);
        ai += __shfl_xor_sync(0xffffffffu, ai, 2);
        ai += __shfl_xor_sync(0xffffffffu, ai, 4);
        aj += __shfl_xor_sync(0xffffffffu, aj, 1);
        aj += __shfl_xor_sync(0xffffffffu, aj, 2);
        aj += __shfl_xor_sync(0xffffffffu, aj, 4);
        if (cg == 0) { g_ai[node] = ai; g_aj[node] = aj; }
    }
}

// ---------------------------------------------------------------------------
// Kernel 2: one warp per node — segment softmax over 32 edges + self loop,
// fp16 gather (half the L2 traffic), fp32 accumulate, bias, BN partials.
// ---------------------------------------------------------------------------
__global__ __launch_bounds__(256) void k2_aggr(
    const void* __restrict__ eidx, const float* __restrict__ bias,
    float* __restrict__ out)
{
    __shared__ float s_w[8][33];
    __shared__ int   s_s[8][33];
    __shared__ float s_red[8][OUTC];
    __shared__ float s_red2[8][OUTC];

    const int tid  = threadIdx.x;
    const int wid  = tid >> 5;
    const int lane = tid & 31;
    const int n    = blockIdx.x * 8 + wid;
    const int e    = n * TOPK + lane;

    int src;
    if (g_idx64) src = (int)((const long long*)eidx)[e];
    else         src = ((const int*)eidx)[e];

    const float ain = g_ai[n];
    float al = ain + g_aj[src];
    al = (al >= 0.f) ? al : 0.2f * al;
    float as = ain + g_aj[n];
    as = (as >= 0.f) ? as : 0.2f * as;

    float m = al;
    #pragma unroll
    for (int o = 16; o > 0; o >>= 1) m = fmaxf(m, __shfl_xor_sync(0xffffffffu, m, o));
    m = fmaxf(m, as);

    float w  = __expf(al - m);
    float ws = __expf(as - m);
    float sum = w;
    #pragma unroll
    for (int o = 16; o > 0; o >>= 1) sum += __shfl_xor_sync(0xffffffffu, sum, o);
    const float inv = 1.f / (sum + ws + 1e-16f);

    s_w[wid][lane] = w;
    s_s[wid][lane] = src;
    if (lane == 0) { s_w[wid][32] = ws; s_s[wid][32] = n; }
    __syncwarp();

    float2 acc = make_float2(0.f, 0.f);
    #pragma unroll 8
    for (int k = 0; k < 33; ++k) {
        float we = s_w[wid][k];
        int   s  = s_s[wid][k];
        float2 v = __half22float2(g_xlin_h[(size_t)s * 32 + lane]);
        acc.x += we * v.x;
        acc.y += we * v.y;
    }

    float2 b = ((const float2*)bias)[lane];
    float2 r;
    r.x = acc.x * inv + b.x;
    r.y = acc.y * inv + b.y;
    ((float2*)out)[(size_t)n * 32 + lane] = r;

    s_red [wid][2 * lane]     = r.x;
    s_red [wid][2 * lane + 1] = r.y;
    s_red2[wid][2 * lane]     = r.x * r.x;
    s_red2[wid][2 * lane + 1] = r.y * r.y;
    __syncthreads();

    if (tid < OUTC) {
        float t = 0.f;
        #pragma unroll
        for (int ww = 0; ww < 8; ++ww) t += s_red[ww][tid];
        atomicAdd(&g_bnsum[tid], t);
    } else if (tid < 2 * OUTC) {
        const int c = tid - OUTC;
        float t = 0.f;
        #pragma unroll
        for (int ww = 0; ww < 8; ++ww) t += s_red2[ww][c];
        atomicAdd(&g_bnsq[c], t);
    }
}

// ---------------------------------------------------------------------------
// Kernel 3: BatchNorm (training-mode batch stats, biased var) + ReLU, in place.
// ---------------------------------------------------------------------------
__global__ __launch_bounds__(256) void k3_bn(
    float* __restrict__ out,
    const float* __restrict__ gamma, const float* __restrict__ beta)
{
    const int i = blockIdx.x * 256 + threadIdx.x;      // over float4s
    if (i >= NN * OUTC / 4) return;
    const int c0 = (i & 15) * 4;
    float4 v = ((const float4*)out)[i];
    const float invN = 1.0f / (float)NN;
    float vv[4] = {v.x, v.y, v.z, v.w};
    float rr[4];
    #pragma unroll
    for (int j = 0; j < 4; ++j) {
        int c = c0 + j;
        float mu  = g_bnsum[c] * invN;
        float var = g_bnsq[c] * invN - mu * mu;
        float sc  = gamma[c] * rsqrtf(var + BN_EPS);
        float sh  = beta[c] - mu * sc;
        rr[j] = fmaxf(vv[j] * sc + sh, 0.f);
    }
    ((float4*)out)[i] = make_float4(rr[0], rr[1], rr[2], rr[3]);
}

// ---------------------------------------------------------------------------
extern "C" void kernel_launch(void* const* d_in, const int* in_sizes, int n_in,
                              void* d_out, int out_size)
{
    const float* x     = (const float*)d_in[0];
    const float* emb   = (const float*)d_in[1];
    const void*  ei    = d_in[2];
    const float* lw    = (const float*)d_in[3];
    const float* atti  = (const float*)d_in[4];
    const float* attj  = (const float*)d_in[5];
    const float* atemi = (const float*)d_in[6];
    const float* atemj = (const float*)d_in[7];
    const float* bias  = (const float*)d_in[8];
    const float* gamma = (const float*)d_in[9];
    const float* beta  = (const float*)d_in[10];
    float* out = (float*)d_out;

    k0_prep<<<1, 256>>>(lw, ei);
    k1_gemm<<<(NN + 127) / 128, 256>>>(x, emb, atti, attj, atemi, atemj);
    k2_aggr<<<NN / 8, 256>>>(ei, bias, out);
    k3_bn<<<(NN * OUTC / 4 + 255) / 256, 256>>>(out, gamma, beta);
}

// round 15
// speedup vs baseline: 1.1418x; 1.1418x over previous
#include <cuda_runtime.h>
#include <cuda_fp16.h>

#define NN 50000
#define TOPK 32
#define INC 128
#define OUTC 64
#define BN_EPS 1e-5f
#define WLD 66                          // s_w row pitch (floats): even -> 8B-aligned b64

// scratch (static __device__: allocation-free per harness rules)
__device__ __half2 g_xlin_h[NN * 32];   // x_lin in fp16: halves k2 gather traffic
__device__ float g_ai[NN];
__device__ float g_aj[NN];
__device__ float g_bnsum[OUTC];
__device__ float g_bnsq[OUTC];
__device__ int   g_idx64;

// packed f32x2 ops (Blackwell sm_10x; FFMA2 only reachable via PTX)
#define FMA_F32X2(acc, a, b) \
    asm("fma.rn.f32x2 %0, %1, %2, %0;" : "+l"(acc) : "l"(a), "l"(b))
#define DUP_F32X2(out, v) \
    asm("mov.b64 %0, {%1, %1};" : "=l"(out) : "r"(__float_as_uint(v)))
#define UNPACK_F32X2(lo, hi, in) \
    asm("mov.b64 {%0, %1}, %2;" : "=r"(lo), "=r"(hi) : "l"(in))

// ---------------------------------------------------------------------------
// Kernel 1: x_lin = x @ W^T, SIMT register-tiled with packed f32x2 FMAs.
// R9 config (best measured): block = 128 thr, 128 nodes x 64 ch, thread =
// 8 nodes x 8 channels (4 channel PAIRS at c = cg*2 + 16j -> conflict-free
// b64 W loads). k0 is fused away: each block transposes W from lin_w into
// smem (ld=66: 2-way write conflicts max, b64-aligned reads); block 0 also
// zeroes BN accumulators and detects index width (k2 runs strictly after).
// Epilogue: fp16 xlin write + per-node attention scalars a_i / a_j (fp32).
// ---------------------------------------------------------------------------
__global__ __launch_bounds__(128) void k1_gemm(
    const float* __restrict__ x, const float* __restrict__ emb,
    const float* __restrict__ lin_w, const void* __restrict__ eidx,
    const float* __restrict__ att_i, const float* __restrict__ att_j,
    const float* __restrict__ att_em_i, const float* __restrict__ att_em_j)
{
    __shared__ float s_w[INC * WLD];      // 33 KB, [k][66]
    __shared__ float s_x[16 * 128];       // 8 KB,  [kk][node]
    __shared__ float s_att[4][OUTC];

    const int tid = threadIdx.x;

    {   // transpose W: lin_w[c][k] -> s_w[k*WLD + c]; coalesced LDG, <=2-way STS
        const int k = tid;                // 128 threads = 128 k values
        #pragma unroll 8
        for (int c = 0; c < OUTC; ++c)
            s_w[k * WLD + c] = lin_w[c * INC + k];
    }
    if (tid < OUTC) {
        s_att[0][tid] = att_i[tid];
        s_att[1][tid] = att_j[tid];
        s_att[2][tid] = att_em_i[tid];
        s_att[3][tid] = att_em_j[tid];
    }
    if (blockIdx.x == 0) {                // safe: k2 launches after k1 completes
        if (tid < OUTC) { g_bnsum[tid] = 0.f; g_bnsq[tid] = 0.f; }
        if (tid == 0) {
            // int64 data has zero high words (all indices < 50000);
            // int32 data has words[1,3,5,7] = src[1,3,5,7] >= 1 always.
            const unsigned* w = (const unsigned*)eidx;
            g_idx64 = ((w[1] | w[3] | w[5] | w[7]) == 0u) ? 1 : 0;
        }
    }

    int nbase = blockIdx.x * 128;
    if (nbase + 128 > NN) nbase = NN - 128;   // overlap rows: identical rewrite, benign

    const int ng  = tid >> 3;                 // 16 node-groups of 8
    const int cg  = tid & 7;                  // 8 channel-groups
    const int nd0 = ng << 3;

    unsigned long long acc[8][4];
    #pragma unroll
    for (int n = 0; n < 8; ++n)
        #pragma unroll
        for (int j = 0; j < 4; ++j) acc[n][j] = 0ULL;   // packed {+0,+0}

    const float4* xrow = (const float4*)(x + (size_t)(nbase + tid) * INC);
    float4 v0 = xrow[0], v1 = xrow[1], v2 = xrow[2], v3 = xrow[3];

    #pragma unroll 1
    for (int kc = 0; kc < 8; ++kc) {
        __syncthreads();
        s_x[ 0 * 128 + tid] = v0.x; s_x[ 1 * 128 + tid] = v0.y;
        s_x[ 2 * 128 + tid] = v0.z; s_x[ 3 * 128 + tid] = v0.w;
        s_x[ 4 * 128 + tid] = v1.x; s_x[ 5 * 128 + tid] = v1.y;
        s_x[ 6 * 128 + tid] = v1.z; s_x[ 7 * 128 + tid] = v1.w;
        s_x[ 8 * 128 + tid] = v2.x; s_x[ 9 * 128 + tid] = v2.y;
        s_x[10 * 128 + tid] = v2.z; s_x[11 * 128 + tid] = v2.w;
        s_x[12 * 128 + tid] = v3.x; s_x[13 * 128 + tid] = v3.y;
        s_x[14 * 128 + tid] = v3.z; s_x[15 * 128 + tid] = v3.w;
        __syncthreads();

        if (kc < 7) {                          // prefetch next chunk (overlaps compute)
            v0 = xrow[(kc + 1) * 4 + 0];
            v1 = xrow[(kc + 1) * 4 + 1];
            v2 = xrow[(kc + 1) * 4 + 2];
            v3 = xrow[(kc + 1) * 4 + 3];
        }

        #pragma unroll
        for (int kk = 0; kk < 16; ++kk) {
            const float4* xp = (const float4*)&s_x[kk * 128 + nd0];
            float4 xa = xp[0], xb = xp[1];
            unsigned long long xd[8];
            DUP_F32X2(xd[0], xa.x); DUP_F32X2(xd[1], xa.y);
            DUP_F32X2(xd[2], xa.z); DUP_F32X2(xd[3], xa.w);
            DUP_F32X2(xd[4], xb.x); DUP_F32X2(xd[5], xb.y);
            DUP_F32X2(xd[6], xb.z); DUP_F32X2(xd[7], xb.w);

            const unsigned long long* wp =
                (const unsigned long long*)&s_w[(kc * 16 + kk) * WLD];
            unsigned long long w0 = wp[cg];
            unsigned long long w1 = wp[cg + 8];
            unsigned long long w2 = wp[cg + 16];
            unsigned long long w3 = wp[cg + 24];

            #pragma unroll
            for (int n = 0; n < 8; ++n) {
                FMA_F32X2(acc[n][0], xd[n], w0);
                FMA_F32X2(acc[n][1], xd[n], w1);
                FMA_F32X2(acc[n][2], xd[n], w2);
                FMA_F32X2(acc[n][3], xd[n], w3);
            }
        }
    }

    // epilogue: fp16 xlin write + attention scalars (8-lane shuffle reduce)
    #pragma unroll
    for (int n = 0; n < 8; ++n) {
        const int node = nbase + nd0 + n;
        __half2*      xlo  = g_xlin_h + (size_t)node * 32;
        const float2* erow = (const float2*)emb + (size_t)node * 32;
        float ai = 0.f, aj = 0.f;
        #pragma unroll
        for (int j = 0; j < 4; ++j) {
            unsigned lo_u, hi_u;
            UNPACK_F32X2(lo_u, hi_u, acc[n][j]);
            float lo = __uint_as_float(lo_u), hi = __uint_as_float(hi_u);
            const int c = cg * 2 + 16 * j;
            xlo[cg + 8 * j] = __floats2half2_rn(lo, hi);
            float2 e = erow[cg + 8 * j];
            ai += lo * s_att[0][c] + hi * s_att[0][c + 1]
                + e.x * s_att[2][c] + e.y * s_att[2][c + 1];
            aj += lo * s_att[1][c] + hi * s_att[1][c + 1]
                + e.x * s_att[3][c] + e.y * s_att[3][c + 1];
        }
        ai += __shfl_xor_sync(0xffffffffu, ai, 1);
        ai += __shfl_xor_sync(0xffffffffu, ai, 2);
        ai += __shfl_xor_sync(0xffffffffu, ai, 4);
        aj += __shfl_xor_sync(0xffffffffu, aj, 1);
        aj += __shfl_xor_sync(0xffffffffu, aj, 2);
        aj += __shfl_xor_sync(0xffffffffu, aj, 4);
        if (cg == 0) { g_ai[node] = ai; g_aj[node] = aj; }
    }
}

// ---------------------------------------------------------------------------
// Kernel 2: one warp per node — segment softmax over 32 edges + self loop,
// fp16 gather (half the L2 traffic), fp32 accumulate, bias, BN partials.
// ---------------------------------------------------------------------------
__global__ __launch_bounds__(256) void k2_aggr(
    const void* __restrict__ eidx, const float* __restrict__ bias,
    float* __restrict__ out)
{
    __shared__ float s_w[8][33];
    __shared__ int   s_s[8][33];
    __shared__ float s_red[8][OUTC];
    __shared__ float s_red2[8][OUTC];

    const int tid  = threadIdx.x;
    const int wid  = tid >> 5;
    const int lane = tid & 31;
    const int n    = blockIdx.x * 8 + wid;
    const int e    = n * TOPK + lane;

    int src;
    if (g_idx64) src = (int)((const long long*)eidx)[e];
    else         src = ((const int*)eidx)[e];

    const float ain = g_ai[n];
    float al = ain + g_aj[src];
    al = (al >= 0.f) ? al : 0.2f * al;
    float as = ain + g_aj[n];
    as = (as >= 0.f) ? as : 0.2f * as;

    float m = al;
    #pragma unroll
    for (int o = 16; o > 0; o >>= 1) m = fmaxf(m, __shfl_xor_sync(0xffffffffu, m, o));
    m = fmaxf(m, as);

    float w  = __expf(al - m);
    float ws = __expf(as - m);
    float sum = w;
    #pragma unroll
    for (int o = 16; o > 0; o >>= 1) sum += __shfl_xor_sync(0xffffffffu, sum, o);
    const float inv = 1.f / (sum + ws + 1e-16f);

    s_w[wid][lane] = w;
    s_s[wid][lane] = src;
    if (lane == 0) { s_w[wid][32] = ws; s_s[wid][32] = n; }
    __syncwarp();

    float2 acc = make_float2(0.f, 0.f);
    #pragma unroll 8
    for (int k = 0; k < 33; ++k) {
        float we = s_w[wid][k];
        int   s  = s_s[wid][k];
        float2 v = __half22float2(g_xlin_h[(size_t)s * 32 + lane]);
        acc.x += we * v.x;
        acc.y += we * v.y;
    }

    float2 b = ((const float2*)bias)[lane];
    float2 r;
    r.x = acc.x * inv + b.x;
    r.y = acc.y * inv + b.y;
    ((float2*)out)[(size_t)n * 32 + lane] = r;

    s_red [wid][2 * lane]     = r.x;
    s_red [wid][2 * lane + 1] = r.y;
    s_red2[wid][2 * lane]     = r.x * r.x;
    s_red2[wid][2 * lane + 1] = r.y * r.y;
    __syncthreads();

    if (tid < OUTC) {
        float t = 0.f;
        #pragma unroll
        for (int ww = 0; ww < 8; ++ww) t += s_red[ww][tid];
        atomicAdd(&g_bnsum[tid], t);
    } else if (tid < 2 * OUTC) {
        const int c = tid - OUTC;
        float t = 0.f;
        #pragma unroll
        for (int ww = 0; ww < 8; ++ww) t += s_red2[ww][c];
        atomicAdd(&g_bnsq[c], t);
    }
}

// ---------------------------------------------------------------------------
// Kernel 3: BatchNorm (training-mode batch stats, biased var) + ReLU,
// in place; 2 independent float4s per thread for MLP.
// ---------------------------------------------------------------------------
__global__ __launch_bounds__(256) void k3_bn(
    float* __restrict__ out,
    const float* __restrict__ gamma, const float* __restrict__ beta)
{
    const int base = blockIdx.x * 512 + threadIdx.x;   // over float4s, x2
    const float invN = 1.0f / (float)NN;
    #pragma unroll
    for (int h = 0; h < 2; ++h) {
        const int i = base + h * 256;
        if (i >= NN * OUTC / 4) break;
        const int c0 = (i & 15) * 4;
        float4 v = ((const float4*)out)[i];
        float vv[4] = {v.x, v.y, v.z, v.w};
        float rr[4];
        #pragma unroll
        for (int j = 0; j < 4; ++j) {
            int c = c0 + j;
            float mu  = g_bnsum[c] * invN;
            float var = g_bnsq[c] * invN - mu * mu;
            float sc  = gamma[c] * rsqrtf(var + BN_EPS);
            float sh  = beta[c] - mu * sc;
            rr[j] = fmaxf(vv[j] * sc + sh, 0.f);
        }
        ((float4*)out)[i] = make_float4(rr[0], rr[1], rr[2], rr[3]);
    }
}

// ---------------------------------------------------------------------------
extern "C" void kernel_launch(void* const* d_in, const int* in_sizes, int n_in,
                              void* d_out, int out_size)
{
    const float* x     = (const float*)d_in[0];
    const float* emb   = (const float*)d_in[1];
    const void*  ei    = d_in[2];
    const float* lw    = (const float*)d_in[3];
    const float* atti  = (const float*)d_in[4];
    const float* attj  = (const float*)d_in[5];
    const float* atemi = (const float*)d_in[6];
    const float* atemj = (const float*)d_in[7];
    const float* bias  = (const float*)d_in[8];
    const float* gamma = (const float*)d_in[9];
    const float* beta  = (const float*)d_in[10];
    float* out = (float*)d_out;

    k1_gemm<<<(NN + 127) / 128, 128>>>(x, emb, lw, ei, atti, attj, atemi, atemj);
    k2_aggr<<<NN / 8, 256>>>(ei, bias, out);
    k3_bn<<<(NN * OUTC / 4 + 511) / 512, 256>>>(out, gamma, beta);
}

// round 16
// speedup vs baseline: 1.1697x; 1.0244x over previous
#include <cuda_runtime.h>
#include <cuda_fp16.h>

#define NN 50000
#define TOPK 32
#define INC 128
#define OUTC 64
#define BN_EPS 1e-5f
#define WLD 66                          // s_w row pitch (floats): even -> 8B-aligned b64

typedef unsigned long long ull;

// scratch (static __device__: allocation-free per harness rules)
__device__ __half2 g_xlin_h[NN * 32];   // x_lin in fp16: halves k2 gather traffic
__device__ float g_ai[NN];
__device__ float g_aj[NN];
__device__ float g_bnsum[OUTC];
__device__ float g_bnsq[OUTC];
__device__ int   g_idx64;

// packed f32x2 ops (Blackwell sm_10x; FFMA2 only reachable via PTX)
#define FMA_F32X2(acc, a, b) \
    asm("fma.rn.f32x2 %0, %1, %2, %0;" : "+l"(acc) : "l"(a), "l"(b))
#define DUP_F32X2(out, v) \
    asm("mov.b64 %0, {%1, %1};" : "=l"(out) : "r"(__float_as_uint(v)))
#define UNPACK_F32X2(lo, hi, in) \
    asm("mov.b64 {%0, %1}, %2;" : "=r"(lo), "=r"(hi) : "l"(in))

// ---------------------------------------------------------------------------
// Kernel 1: x_lin = x @ W^T, register-tiled FFMA2, software-pipelined.
// Block = 128 thr, 128 nodes x 64 ch; thread = 8 nodes x 8 channels
// (4 channel PAIRS at c = cg*2 + 16j -> conflict-free b64 W loads).
// ncu showed fma-pipe busy only 33% (latency-bound at 3 warps/SMSP), so:
//  - kk loop explicitly prefetches next iteration's 6 smem loads into regs
//    while 32 independent FFMA2s issue (covers the 29-cyc LDS latency);
//  - s_x is double-buffered: one sync per k-chunk, STS overlapped w/ compute.
// Epilogue: fp16 xlin write + per-node attention scalars a_i / a_j (fp32).
// ---------------------------------------------------------------------------
__global__ __launch_bounds__(128) void k1_gemm(
    const float* __restrict__ x, const float* __restrict__ emb,
    const float* __restrict__ lin_w, const void* __restrict__ eidx,
    const float* __restrict__ att_i, const float* __restrict__ att_j,
    const float* __restrict__ att_em_i, const float* __restrict__ att_em_j)
{
    __shared__ float s_w[INC * WLD];      // 33 KB, [k][66]
    __shared__ float s_x[2][16 * 128];    // 16 KB, double-buffered [kk][node]
    __shared__ float s_att[4][OUTC];

    const int tid = threadIdx.x;

    {   // transpose W: lin_w[c][k] -> s_w[k*WLD + c]; coalesced LDG, <=2-way STS
        const int k = tid;
        #pragma unroll 8
        for (int c = 0; c < OUTC; ++c)
            s_w[k * WLD + c] = lin_w[c * INC + k];
    }
    if (tid < OUTC) {
        s_att[0][tid] = att_i[tid];
        s_att[1][tid] = att_j[tid];
        s_att[2][tid] = att_em_i[tid];
        s_att[3][tid] = att_em_j[tid];
    }
    if (blockIdx.x == 0) {                // safe: k2 launches after k1 completes
        if (tid < OUTC) { g_bnsum[tid] = 0.f; g_bnsq[tid] = 0.f; }
        if (tid == 0) {
            // int64 data has zero high words (all indices < 50000);
            // int32 data has words[1,3,5,7] = src[1,3,5,7] >= 1 always.
            const unsigned* w = (const unsigned*)eidx;
            g_idx64 = ((w[1] | w[3] | w[5] | w[7]) == 0u) ? 1 : 0;
        }
    }

    int nbase = blockIdx.x * 128;
    if (nbase + 128 > NN) nbase = NN - 128;   // overlap rows: identical rewrite, benign

    const int ng  = tid >> 3;                 // 16 node-groups of 8
    const int cg  = tid & 7;                  // 8 channel-groups
    const int nd0 = ng << 3;

    ull acc[8][4];
    #pragma unroll
    for (int n = 0; n < 8; ++n)
        #pragma unroll
        for (int j = 0; j < 4; ++j) acc[n][j] = 0ULL;   // packed {+0,+0}

    const float4* xrow = (const float4*)(x + (size_t)(nbase + tid) * INC);
    float4 v0 = xrow[0], v1 = xrow[1], v2 = xrow[2], v3 = xrow[3];

    {   // stage chunk 0 into buffer 0
        float* sx = s_x[0];
        sx[ 0 * 128 + tid] = v0.x; sx[ 1 * 128 + tid] = v0.y;
        sx[ 2 * 128 + tid] = v0.z; sx[ 3 * 128 + tid] = v0.w;
        sx[ 4 * 128 + tid] = v1.x; sx[ 5 * 128 + tid] = v1.y;
        sx[ 6 * 128 + tid] = v1.z; sx[ 7 * 128 + tid] = v1.w;
        sx[ 8 * 128 + tid] = v2.x; sx[ 9 * 128 + tid] = v2.y;
        sx[10 * 128 + tid] = v2.z; sx[11 * 128 + tid] = v2.w;
        sx[12 * 128 + tid] = v3.x; sx[13 * 128 + tid] = v3.y;
        sx[14 * 128 + tid] = v3.z; sx[15 * 128 + tid] = v3.w;
    }
    v0 = xrow[4]; v1 = xrow[5]; v2 = xrow[6]; v3 = xrow[7];   // prefetch chunk 1
    __syncthreads();

    #pragma unroll 1
    for (int kc = 0; kc < 8; ++kc) {
        // stage chunk kc+1 into the other buffer (readers use buf kc&1: disjoint)
        if (kc < 7) {
            float* sx = s_x[(kc + 1) & 1];
            sx[ 0 * 128 + tid] = v0.x; sx[ 1 * 128 + tid] = v0.y;
            sx[ 2 * 128 + tid] = v0.z; sx[ 3 * 128 + tid] = v0.w;
            sx[ 4 * 128 + tid] = v1.x; sx[ 5 * 128 + tid] = v1.y;
            sx[ 6 * 128 + tid] = v1.z; sx[ 7 * 128 + tid] = v1.w;
            sx[ 8 * 128 + tid] = v2.x; sx[ 9 * 128 + tid] = v2.y;
            sx[10 * 128 + tid] = v2.z; sx[11 * 128 + tid] = v2.w;
            sx[12 * 128 + tid] = v3.x; sx[13 * 128 + tid] = v3.y;
            sx[14 * 128 + tid] = v3.z; sx[15 * 128 + tid] = v3.w;
            if (kc < 6) {
                v0 = xrow[(kc + 2) * 4 + 0];
                v1 = xrow[(kc + 2) * 4 + 1];
                v2 = xrow[(kc + 2) * 4 + 2];
                v3 = xrow[(kc + 2) * 4 + 3];
            }
        }

        const float* sxc = s_x[kc & 1];

        // preload kk = 0
        float4 xa = *(const float4*)&sxc[nd0];
        float4 xb = *(const float4*)&sxc[nd0 + 4];
        const ull* wp = (const ull*)&s_w[(kc * 16) * WLD];
        ull w0 = wp[cg], w1 = wp[cg + 8], w2 = wp[cg + 16], w3 = wp[cg + 24];

        #pragma unroll
        for (int kk = 0; kk < 16; ++kk) {
            float4 xan, xbn;
            ull w0n, w1n, w2n, w3n;
            if (kk < 15) {                 // prefetch kk+1 while FMAs issue
                const float* nx = &sxc[(kk + 1) * 128 + nd0];
                xan = *(const float4*)nx;
                xbn = *(const float4*)(nx + 4);
                const ull* wpn = (const ull*)&s_w[(kc * 16 + kk + 1) * WLD];
                w0n = wpn[cg];      w1n = wpn[cg + 8];
                w2n = wpn[cg + 16]; w3n = wpn[cg + 24];
            }

            ull xd[8];
            DUP_F32X2(xd[0], xa.x); DUP_F32X2(xd[1], xa.y);
            DUP_F32X2(xd[2], xa.z); DUP_F32X2(xd[3], xa.w);
            DUP_F32X2(xd[4], xb.x); DUP_F32X2(xd[5], xb.y);
            DUP_F32X2(xd[6], xb.z); DUP_F32X2(xd[7], xb.w);

            #pragma unroll
            for (int n = 0; n < 8; ++n) {
                FMA_F32X2(acc[n][0], xd[n], w0);
                FMA_F32X2(acc[n][1], xd[n], w1);
                FMA_F32X2(acc[n][2], xd[n], w2);
                FMA_F32X2(acc[n][3], xd[n], w3);
            }

            if (kk < 15) {
                xa = xan; xb = xbn;
                w0 = w0n; w1 = w1n; w2 = w2n; w3 = w3n;
            }
        }
        __syncthreads();
    }

    // epilogue: fp16 xlin write + attention scalars (8-lane shuffle reduce)
    #pragma unroll
    for (int n = 0; n < 8; ++n) {
        const int node = nbase + nd0 + n;
        __half2*      xlo  = g_xlin_h + (size_t)node * 32;
        const float2* erow = (const float2*)emb + (size_t)node * 32;
        float ai = 0.f, aj = 0.f;
        #pragma unroll
        for (int j = 0; j < 4; ++j) {
            unsigned lo_u, hi_u;
            UNPACK_F32X2(lo_u, hi_u, acc[n][j]);
            float lo = __uint_as_float(lo_u), hi = __uint_as_float(hi_u);
            const int c = cg * 2 + 16 * j;
            xlo[cg + 8 * j] = __floats2half2_rn(lo, hi);
            float2 e = erow[cg + 8 * j];
            ai += lo * s_att[0][c] + hi * s_att[0][c + 1]
                + e.x * s_att[2][c] + e.y * s_att[2][c + 1];
            aj += lo * s_att[1][c] + hi * s_att[1][c + 1]
                + e.x * s_att[3][c] + e.y * s_att[3][c + 1];
        }
        ai += __shfl_xor_sync(0xffffffffu, ai, 1);
        ai += __shfl_xor_sync(0xffffffffu, ai, 2);
        ai += __shfl_xor_sync(0xffffffffu, ai, 4);
        aj += __shfl_xor_sync(0xffffffffu, aj, 1);
        aj += __shfl_xor_sync(0xffffffffu, aj, 2);
        aj += __shfl_xor_sync(0xffffffffu, aj, 4);
        if (cg == 0) { g_ai[node] = ai; g_aj[node] = aj; }
    }
}

// ---------------------------------------------------------------------------
// Kernel 2: one warp per node — segment softmax over 32 edges + self loop,
// fp16 gather (half the L2 traffic), fp32 accumulate, bias, BN partials.
// ---------------------------------------------------------------------------
__global__ __launch_bounds__(256) void k2_aggr(
    const void* __restrict__ eidx, const float* __restrict__ bias,
    float* __restrict__ out)
{
    __shared__ float s_w[8][33];
    __shared__ int   s_s[8][33];
    __shared__ float s_red[8][OUTC];
    __shared__ float s_red2[8][OUTC];

    const int tid  = threadIdx.x;
    const int wid  = tid >> 5;
    const int lane = tid & 31;
    const int n    = blockIdx.x * 8 + wid;
    const int e    = n * TOPK + lane;

    int src;
    if (g_idx64) src = (int)((const long long*)eidx)[e];
    else         src = ((const int*)eidx)[e];

    const float ain = g_ai[n];
    float al = ain + g_aj[src];
    al = (al >= 0.f) ? al : 0.2f * al;
    float as = ain + g_aj[n];
    as = (as >= 0.f) ? as : 0.2f * as;

    float m = al;
    #pragma unroll
    for (int o = 16; o > 0; o >>= 1) m = fmaxf(m, __shfl_xor_sync(0xffffffffu, m, o));
    m = fmaxf(m, as);

    float w  = __expf(al - m);
    float ws = __expf(as - m);
    float sum = w;
    #pragma unroll
    for (int o = 16; o > 0; o >>= 1) sum += __shfl_xor_sync(0xffffffffu, sum, o);
    const float inv = 1.f / (sum + ws + 1e-16f);

    s_w[wid][lane] = w;
    s_s[wid][lane] = src;
    if (lane == 0) { s_w[wid][32] = ws; s_s[wid][32] = n; }
    __syncwarp();

    float2 acc = make_float2(0.f, 0.f);
    #pragma unroll 8
    for (int k = 0; k < 33; ++k) {
        float we = s_w[wid][k];
        int   s  = s_s[wid][k];
        float2 v = __half22float2(g_xlin_h[(size_t)s * 32 + lane]);
        acc.x += we * v.x;
        acc.y += we * v.y;
    }

    float2 b = ((const float2*)bias)[lane];
    float2 r;
    r.x = acc.x * inv + b.x;
    r.y = acc.y * inv + b.y;
    ((float2*)out)[(size_t)n * 32 + lane] = r;

    s_red [wid][2 * lane]     = r.x;
    s_red [wid][2 * lane + 1] = r.y;
    s_red2[wid][2 * lane]     = r.x * r.x;
    s_red2[wid][2 * lane + 1] = r.y * r.y;
    __syncthreads();

    if (tid < OUTC) {
        float t = 0.f;
        #pragma unroll
        for (int ww = 0; ww < 8; ++ww) t += s_red[ww][tid];
        atomicAdd(&g_bnsum[tid], t);
    } else if (tid < 2 * OUTC) {
        const int c = tid - OUTC;
        float t = 0.f;
        #pragma unroll
        for (int ww = 0; ww < 8; ++ww) t += s_red2[ww][c];
        atomicAdd(&g_bnsq[c], t);
    }
}

// ---------------------------------------------------------------------------
// Kernel 3: BatchNorm (training-mode batch stats, biased var) + ReLU,
// in place; 2 independent float4s per thread for MLP.
// ---------------------------------------------------------------------------
__global__ __launch_bounds__(256) void k3_bn(
    float* __restrict__ out,
    const float* __restrict__ gamma, const float* __restrict__ beta)
{
    const int base = blockIdx.x * 512 + threadIdx.x;   // over float4s, x2
    const float invN = 1.0f / (float)NN;
    #pragma unroll
    for (int h = 0; h < 2; ++h) {
        const int i = base + h * 256;
        if (i >= NN * OUTC / 4) break;
        const int c0 = (i & 15) * 4;
        float4 v = ((const float4*)out)[i];
        float vv[4] = {v.x, v.y, v.z, v.w};
        float rr[4];
        #pragma unroll
        for (int j = 0; j < 4; ++j) {
            int c = c0 + j;
            float mu  = g_bnsum[c] * invN;
            float var = g_bnsq[c] * invN - mu * mu;
            float sc  = gamma[c] * rsqrtf(var + BN_EPS);
            float sh  = beta[c] - mu * sc;
            rr[j] = fmaxf(vv[j] * sc + sh, 0.f);
        }
        ((float4*)out)[i] = make_float4(rr[0], rr[1], rr[2], rr[3]);
    }
}

// ---------------------------------------------------------------------------
extern "C" void kernel_launch(void* const* d_in, const int* in_sizes, int n_in,
                              void* d_out, int out_size)
{
    const float* x     = (const float*)d_in[0];
    const float* emb   = (const float*)d_in[1];
    const void*  ei    = d_in[2];
    const float* lw    = (const float*)d_in[3];
    const float* atti  = (const float*)d_in[4];
    const float* attj  = (const float*)d_in[5];
    const float* atemi = (const float*)d_in[6];
    const float* atemj = (const float*)d_in[7];
    const float* bias  = (const float*)d_in[8];
    const float* gamma = (const float*)d_in[9];
    const float* beta  = (const float*)d_in[10];
    float* out = (float*)d_out;

    k1_gemm<<<(NN + 127) / 128, 128>>>(x, emb, lw, ei, atti, attj, atemi, atemj);
    k2_aggr<<<NN / 8, 256>>>(ei, bias, out);
    k3_bn<<<(NN * OUTC / 4 + 511) / 512, 256>>>(out, gamma, beta);
}